// round 1
// baseline (speedup 1.0000x reference)
#include <cuda_runtime.h>
#include <cuda_bf16.h>
#include <math.h>

#define N_TAGS 48
#define ROOT 46
#define END_TAG 47
#define BATCH 512
#define MAXT 256
#define NTHREADS 64

__global__ __launch_bounds__(NTHREADS)
void crf_nll_kernel(const float* __restrict__ feats,
                    const int* __restrict__ tags,
                    const int* __restrict__ lengths,
                    const float* __restrict__ lt,
                    float* __restrict__ out)
{
    const int b = blockIdx.x;
    const int j = threadIdx.x;           // tag lane (0..47 active)
    const int wid = j >> 5;
    const bool active = (j < N_TAGS);

    __shared__ float se[N_TAGS];     // exp(alpha_i - m)
    __shared__ float wred[2];        // cross-warp reduce scratch
    __shared__ float gred[2];        // gold partial sums
    __shared__ float s_gold;

    const int len = lengths[b];
    const long fbase = (long)b * MAXT * N_TAGS;
    const int tbase = b * MAXT;

    // ---------------- gold score (all 64 threads, t-strided) ----------------
    {
        float g = 0.0f;
        for (int t = j; t < MAXT; t += NTHREADS) {
            if (t < len) {
                int tg = tags[tbase + t];
                g += feats[fbase + t * N_TAGS + tg];
                if (t >= 1) {
                    int tp = tags[tbase + t - 1];
                    g += lt[tp * N_TAGS + tg];
                }
            }
        }
        if (j == 0) {
            int t0 = tags[tbase];
            int tl = tags[tbase + len - 1];
            g += lt[ROOT * N_TAGS + t0] + lt[tl * N_TAGS + END_TAG];
        }
        // warp butterfly sum
        #pragma unroll
        for (int off = 16; off; off >>= 1)
            g += __shfl_xor_sync(0xffffffffu, g, off);
        if ((j & 31) == 0) gred[wid] = g;
        __syncthreads();
        if (j == 0) s_gold = gred[0] + gred[1];
        // (s_gold read only by thread 0 at the end, after later syncs)
    }

    // ---------------- load E column into registers ----------------
    float E[N_TAGS];
    float lt_end = 0.0f;
    if (active) {
        #pragma unroll
        for (int i = 0; i < N_TAGS; i++)
            E[i] = __expf(lt[i * N_TAGS + j]);
        lt_end = lt[j * N_TAGS + END_TAG];
    } else {
        #pragma unroll
        for (int i = 0; i < N_TAGS; i++) E[i] = 0.0f;
    }

    // ---------------- alpha init ----------------
    float alpha = -INFINITY;
    if (active)
        alpha = lt[ROOT * N_TAGS + j] + feats[fbase + j];

    // prefetch feats for t=1
    float fnext = 0.0f;
    if (active && len > 1) fnext = feats[fbase + N_TAGS + j];

    __syncthreads();   // protect gred before reuse of wred pattern

    // ---------------- forward recurrence ----------------
    for (int t = 1; t < len; ++t) {
        float fcur = fnext;
        if (active && (t + 1) < len)
            fnext = feats[fbase + (long)(t + 1) * N_TAGS + j];

        // block max of alpha (inactive lanes hold -inf)
        float v = alpha;
        #pragma unroll
        for (int off = 16; off; off >>= 1)
            v = fmaxf(v, __shfl_xor_sync(0xffffffffu, v, off));
        if ((j & 31) == 0) wred[wid] = v;
        __syncthreads();
        float m = fmaxf(wred[0], wred[1]);

        float e = __expf(alpha - m);   // 0 for -inf lanes
        if (active) se[j] = e;
        __syncthreads();

        // dot(se, E_col_j) with 4 accumulators
        float s0 = 0.f, s1 = 0.f, s2 = 0.f, s3 = 0.f;
        #pragma unroll
        for (int i = 0; i < N_TAGS; i += 4) {
            s0 = fmaf(se[i + 0], E[i + 0], s0);
            s1 = fmaf(se[i + 1], E[i + 1], s1);
            s2 = fmaf(se[i + 2], E[i + 2], s2);
            s3 = fmaf(se[i + 3], E[i + 3], s3);
        }
        float s = (s0 + s1) + (s2 + s3);

        // s==0 -> -inf (ROOT column & inactive lanes), which is correct
        alpha = m + __logf(s) + fcur;
        __syncthreads();   // se must not be overwritten before all have read
    }

    // ---------------- partition = lse_j(alpha_j + lt[j][END]) ----------------
    float p = active ? (alpha + lt_end) : -INFINITY;
    float v = p;
    #pragma unroll
    for (int off = 16; off; off >>= 1)
        v = fmaxf(v, __shfl_xor_sync(0xffffffffu, v, off));
    if ((j & 31) == 0) wred[wid] = v;
    __syncthreads();
    float m2 = fmaxf(wred[0], wred[1]);

    float ex = __expf(p - m2);
    #pragma unroll
    for (int off = 16; off; off >>= 1)
        ex += __shfl_xor_sync(0xffffffffu, ex, off);
    if ((j & 31) == 0) wred[wid] = ex;
    __syncthreads();

    if (j == 0) {
        float partition = m2 + __logf(wred[0] + wred[1]);
        out[b] = partition - s_gold;
    }
}

extern "C" void kernel_launch(void* const* d_in, const int* in_sizes, int n_in,
                              void* d_out, int out_size)
{
    const float* feats = nullptr;
    const int*   tags = nullptr;
    const int*   lengths = nullptr;
    const float* lt = nullptr;

    for (int i = 0; i < n_in; i++) {
        switch (in_sizes[i]) {
            case BATCH * MAXT * N_TAGS: feats   = (const float*)d_in[i]; break;
            case BATCH * MAXT:          tags    = (const int*)d_in[i];   break;
            case BATCH:                 lengths = (const int*)d_in[i];   break;
            case N_TAGS * N_TAGS:       lt      = (const float*)d_in[i]; break;
        }
    }

    crf_nll_kernel<<<BATCH, NTHREADS>>>(feats, tags, lengths, lt, (float*)d_out);
}

// round 2
// speedup vs baseline: 1.0240x; 1.0240x over previous
#include <cuda_runtime.h>
#include <cuda_bf16.h>
#include <math.h>

#define N_TAGS 48
#define ROOT 46
#define END_TAG 47
#define BATCH 512
#define MAXT 256
#define NTHREADS 64

__global__ __launch_bounds__(NTHREADS)
void crf_nll_kernel(const float* __restrict__ feats,
                    const int* __restrict__ tags,
                    const int* __restrict__ lengths,
                    const float* __restrict__ lt,
                    float* __restrict__ out)
{
    const int b = blockIdx.x;
    const int j = threadIdx.x;           // tag lane (0..47 active)
    const int wid = j >> 5;
    const bool active = (j < N_TAGS);

    __shared__ __align__(16) float se[2][N_TAGS];  // exp(alpha_i - shift), double buffered
    __shared__ float sref[2];        // tag-0 alpha (next shift), double buffered
    __shared__ float wred[2];        // cross-warp reduce scratch (epilogue only)
    __shared__ float gred[2];        // gold partial sums
    __shared__ float s_gold;

    const int len = lengths[b];
    const long fbase = (long)b * MAXT * N_TAGS;
    const int tbase = b * MAXT;

    // ---------------- gold score (all 64 threads, t-strided) ----------------
    {
        float g = 0.0f;
        for (int t = j; t < MAXT; t += NTHREADS) {
            if (t < len) {
                int tg = tags[tbase + t];
                g += feats[fbase + t * N_TAGS + tg];
                if (t >= 1) {
                    int tp = tags[tbase + t - 1];
                    g += lt[tp * N_TAGS + tg];
                }
            }
        }
        if (j == 0) {
            int t0 = tags[tbase];
            int tl = tags[tbase + len - 1];
            g += lt[ROOT * N_TAGS + t0] + lt[tl * N_TAGS + END_TAG];
        }
        #pragma unroll
        for (int off = 16; off; off >>= 1)
            g += __shfl_xor_sync(0xffffffffu, g, off);
        if ((j & 31) == 0) gred[wid] = g;
        // consumed by thread 0 at the very end (after later barriers)
    }

    // ---------------- load E column into registers ----------------
    float E[N_TAGS];
    float lt_end = 0.0f;
    if (active) {
        #pragma unroll
        for (int i = 0; i < N_TAGS; i++)
            E[i] = __expf(lt[i * N_TAGS + j]);
        lt_end = lt[j * N_TAGS + END_TAG];
    } else {
        #pragma unroll
        for (int i = 0; i < N_TAGS; i++) E[i] = 0.0f;
    }

    // ---------------- alpha init ----------------
    float alpha = -INFINITY;
    float f0 = 0.0f;
    if (active) {
        f0 = feats[fbase + j];
        alpha = lt[ROOT * N_TAGS + j] + f0;
    }
    // initial shift: every thread computes tag-0's alpha0 directly
    float shift = lt[ROOT * N_TAGS + 0] + feats[fbase + 0];

    // prefetch feats for t=1
    float fnext = 0.0f;
    if (active && len > 1) fnext = feats[fbase + N_TAGS + j];

    __syncthreads();   // gred visible; also orders init before loop smem use

    // ---------------- forward recurrence (1 barrier/step, no max-reduce) ----
    int p = 0;
    for (int t = 1; t < len; ++t) {
        float fcur = fnext;
        if (active && (t + 1) < len)
            fnext = feats[fbase + (long)(t + 1) * N_TAGS + j];

        // publish exp(alpha - shift); shift lags by one step but stays within
        // ~±35 of the true max -> exact logsumexp in fp32
        float e = __expf(alpha - shift);
        if (active) se[p][j] = e;
        if (j == 0) sref[p] = alpha;       // tag-0 alpha -> next shift
        __syncthreads();

        float shift_next = sref[p];

        // dot(se, E_col_j), vectorized smem reads
        const float4* se4 = (const float4*)se[p];
        float s0 = 0.f, s1 = 0.f, s2 = 0.f, s3 = 0.f;
        #pragma unroll
        for (int i = 0; i < N_TAGS / 4; i++) {
            float4 v = se4[i];
            s0 = fmaf(v.x, E[4 * i + 0], s0);
            s1 = fmaf(v.y, E[4 * i + 1], s1);
            s2 = fmaf(v.z, E[4 * i + 2], s2);
            s3 = fmaf(v.w, E[4 * i + 3], s3);
        }
        float s = (s0 + s1) + (s2 + s3);

        // s==0 -> -inf (ROOT column & inactive lanes), matches reference
        alpha = shift + __logf(s) + fcur;
        shift = shift_next;
        p ^= 1;
    }

    // ---------------- partition = lse_j(alpha_j + lt[j][END]) ----------------
    float pj = active ? (alpha + lt_end) : -INFINITY;
    float v = pj;
    #pragma unroll
    for (int off = 16; off; off >>= 1)
        v = fmaxf(v, __shfl_xor_sync(0xffffffffu, v, off));
    if ((j & 31) == 0) wred[wid] = v;
    __syncthreads();
    float m2 = fmaxf(wred[0], wred[1]);

    float ex = __expf(pj - m2);
    #pragma unroll
    for (int off = 16; off; off >>= 1)
        ex += __shfl_xor_sync(0xffffffffu, ex, off);
    if ((j & 31) == 0) wred[wid] = ex;
    __syncthreads();

    if (j == 0) {
        float partition = m2 + __logf(wred[0] + wred[1]);
        out[b] = partition - (gred[0] + gred[1]);
    }
}

extern "C" void kernel_launch(void* const* d_in, const int* in_sizes, int n_in,
                              void* d_out, int out_size)
{
    const float* feats = nullptr;
    const int*   tags = nullptr;
    const int*   lengths = nullptr;
    const float* lt = nullptr;

    for (int i = 0; i < n_in; i++) {
        switch (in_sizes[i]) {
            case BATCH * MAXT * N_TAGS: feats   = (const float*)d_in[i]; break;
            case BATCH * MAXT:          tags    = (const int*)d_in[i];   break;
            case BATCH:                 lengths = (const int*)d_in[i];   break;
            case N_TAGS * N_TAGS:       lt      = (const float*)d_in[i]; break;
        }
    }

    crf_nll_kernel<<<BATCH, NTHREADS>>>(feats, tags, lengths, lt, (float*)d_out);
}

// round 3
// speedup vs baseline: 1.1562x; 1.1291x over previous
#include <cuda_runtime.h>
#include <cuda_bf16.h>
#include <math.h>

#define N_TAGS 48
#define ROOT 46
#define END_TAG 47
#define BATCH 512
#define MAXT 256
#define NTHREADS 64
#define PF_DEPTH 8

__global__ __launch_bounds__(NTHREADS)
void crf_nll_kernel(const float* __restrict__ feats,
                    const int* __restrict__ tags,
                    const int* __restrict__ lengths,
                    const float* __restrict__ lt,
                    float* __restrict__ out)
{
    const int b = blockIdx.x;
    const int j = threadIdx.x;           // tag lane (0..47 active)
    const int wid = j >> 5;
    const bool active = (j < N_TAGS);

    __shared__ __align__(16) float se[2][N_TAGS];  // exp(alpha - shift), double buffered
    __shared__ float sref[2];        // tag-0 alpha (next shift), double buffered
    __shared__ float wred[2];        // cross-warp reduce scratch (epilogue only)
    __shared__ float gred[2];        // gold partial sums

    const int len = lengths[b];
    const long fbase = (long)b * MAXT * N_TAGS;
    const int tbase = b * MAXT;

    // ---------------- gold score (all 64 threads, t-strided) ----------------
    {
        float g = 0.0f;
        for (int t = j; t < MAXT; t += NTHREADS) {
            if (t < len) {
                int tg = tags[tbase + t];
                g += feats[fbase + t * N_TAGS + tg];
                if (t >= 1) {
                    int tp = tags[tbase + t - 1];
                    g += lt[tp * N_TAGS + tg];
                }
            }
        }
        if (j == 0) {
            int t0 = tags[tbase];
            int tl = tags[tbase + len - 1];
            g += lt[ROOT * N_TAGS + t0] + lt[tl * N_TAGS + END_TAG];
        }
        #pragma unroll
        for (int off = 16; off; off >>= 1)
            g += __shfl_xor_sync(0xffffffffu, g, off);
        if ((j & 31) == 0) gred[wid] = g;
        // consumed by thread 0 at the very end (after later barriers)
    }

    // ---------------- load E column into registers ----------------
    float E[N_TAGS];
    float lt_end = 0.0f;
    if (active) {
        #pragma unroll
        for (int i = 0; i < N_TAGS; i++)
            E[i] = __expf(lt[i * N_TAGS + j]);
        lt_end = lt[j * N_TAGS + END_TAG];
    } else {
        #pragma unroll
        for (int i = 0; i < N_TAGS; i++) E[i] = 0.0f;
    }

    // ---------------- alpha init ----------------
    float alpha = -INFINITY;
    if (active)
        alpha = lt[ROOT * N_TAGS + j] + feats[fbase + j];
    // initial shift: every thread computes tag-0's alpha0 directly
    float shift = lt[ROOT * N_TAGS + 0] + feats[fbase + 0];

    // ---------------- deep feats prefetch pipeline (MLP=PF_DEPTH) ----------
    // fbuf[d] holds feats for timestep t0+d at the top of each chunk.
    float fbuf[PF_DEPTH];
    #pragma unroll
    for (int d = 0; d < PF_DEPTH; d++)
        fbuf[d] = active ? feats[fbase + (long)(1 + d) * N_TAGS + j] : 0.0f;

    __syncthreads();   // gred visible; also orders init before loop smem use

    // ---------------- forward recurrence (1 barrier/step, no max-reduce) ----
    int p = 0;
    for (int t0 = 1; t0 < len; t0 += PF_DEPTH) {
        #pragma unroll
        for (int d = 0; d < PF_DEPTH; d++) {
            const int t = t0 + d;
            if (t >= len) break;            // uniform across block

            float fcur = fbuf[d];
            // refill this slot for t+PF_DEPTH (8 loads always in flight)
            const int tpre = t + PF_DEPTH;
            if (active && tpre < MAXT)
                fbuf[d] = feats[fbase + (long)tpre * N_TAGS + j];

            // publish exp(alpha - shift); shift lags one step but stays
            // within ~±35 of the true max -> exact fp32 logsumexp
            float e = __expf(alpha - shift);
            if (active) se[p][j] = e;
            if (j == 0) sref[p] = alpha;     // tag-0 alpha -> next shift
            __syncthreads();

            float shift_next = sref[p];

            // dot(se, E_col_j), vectorized smem reads
            const float4* se4 = (const float4*)se[p];
            float s0 = 0.f, s1 = 0.f, s2 = 0.f, s3 = 0.f;
            #pragma unroll
            for (int i = 0; i < N_TAGS / 4; i++) {
                float4 v = se4[i];
                s0 = fmaf(v.x, E[4 * i + 0], s0);
                s1 = fmaf(v.y, E[4 * i + 1], s1);
                s2 = fmaf(v.z, E[4 * i + 2], s2);
                s3 = fmaf(v.w, E[4 * i + 3], s3);
            }
            float s = (s0 + s1) + (s2 + s3);

            // s==0 -> -inf (ROOT column & inactive lanes), matches reference
            alpha = shift + __logf(s) + fcur;
            shift = shift_next;
            p ^= 1;
        }
    }

    // ---------------- partition = lse_j(alpha_j + lt[j][END]) ----------------
    float pj = active ? (alpha + lt_end) : -INFINITY;
    float v = pj;
    #pragma unroll
    for (int off = 16; off; off >>= 1)
        v = fmaxf(v, __shfl_xor_sync(0xffffffffu, v, off));
    if ((j & 31) == 0) wred[wid] = v;
    __syncthreads();
    float m2 = fmaxf(wred[0], wred[1]);

    float ex = __expf(pj - m2);
    #pragma unroll
    for (int off = 16; off; off >>= 1)
        ex += __shfl_xor_sync(0xffffffffu, ex, off);
    if ((j & 31) == 0) wred[wid] = ex;
    __syncthreads();

    if (j == 0) {
        float partition = m2 + __logf(wred[0] + wred[1]);
        out[b] = partition - (gred[0] + gred[1]);
    }
}

extern "C" void kernel_launch(void* const* d_in, const int* in_sizes, int n_in,
                              void* d_out, int out_size)
{
    const float* feats = nullptr;
    const int*   tags = nullptr;
    const int*   lengths = nullptr;
    const float* lt = nullptr;

    for (int i = 0; i < n_in; i++) {
        switch (in_sizes[i]) {
            case BATCH * MAXT * N_TAGS: feats   = (const float*)d_in[i]; break;
            case BATCH * MAXT:          tags    = (const int*)d_in[i];   break;
            case BATCH:                 lengths = (const int*)d_in[i];   break;
            case N_TAGS * N_TAGS:       lt      = (const float*)d_in[i]; break;
        }
    }

    crf_nll_kernel<<<BATCH, NTHREADS>>>(feats, tags, lengths, lt, (float*)d_out);
}

// round 4
// speedup vs baseline: 1.2680x; 1.0967x over previous
#include <cuda_runtime.h>
#include <cuda_bf16.h>
#include <math.h>

#define N_TAGS 48
#define ROOT 46
#define END_TAG 47
#define BATCH 512
#define MAXT 256
#define PF 4            // prefetch depth (per tag column): 8 LDGs in flight

__global__ __launch_bounds__(32)
void crf_nll_kernel(const float* __restrict__ feats,
                    const int* __restrict__ tags,
                    const int* __restrict__ lengths,
                    const float* __restrict__ lt,
                    float* __restrict__ out)
{
    const int b = blockIdx.x;
    const int j = threadIdx.x;              // lane 0..31
    const bool hasB = (j < 16);             // lane also owns tag 32+j

    __shared__ __align__(16) float se[2][N_TAGS];   // exp(alpha - shift), double buffered

    const int len = lengths[b];
    const long fbase = (long)b * MAXT * N_TAGS;
    const int tbase = b * MAXT;

    // ---------------- gold score (32 threads, t-strided) ----------------
    float gold;
    {
        float g = 0.0f;
        for (int t = j; t < MAXT; t += 32) {
            if (t < len) {
                int tg = tags[tbase + t];
                g += feats[fbase + t * N_TAGS + tg];
                if (t >= 1) {
                    int tp = tags[tbase + t - 1];
                    g += lt[tp * N_TAGS + tg];
                }
            }
        }
        if (j == 0) {
            int t0 = tags[tbase];
            int tl = tags[tbase + len - 1];
            g += lt[ROOT * N_TAGS + t0] + lt[tl * N_TAGS + END_TAG];
        }
        #pragma unroll
        for (int off = 16; off; off >>= 1)
            g += __shfl_xor_sync(0xffffffffu, g, off);
        gold = g;   // every lane has it
    }

    // ---------------- E columns in registers ----------------
    float Ea[N_TAGS], Eb[N_TAGS];
    #pragma unroll
    for (int i = 0; i < N_TAGS; i++)
        Ea[i] = __expf(lt[i * N_TAGS + j]);
    #pragma unroll
    for (int i = 0; i < N_TAGS; i++)
        Eb[i] = hasB ? __expf(lt[i * N_TAGS + 32 + j]) : 0.0f;

    const float lt_end_a = lt[j * N_TAGS + END_TAG];
    const float lt_end_b = hasB ? lt[(32 + j) * N_TAGS + END_TAG] : 0.0f;

    // ---------------- alpha init ----------------
    float alpha_a = lt[ROOT * N_TAGS + j] + feats[fbase + j];
    float alpha_b = hasB ? (lt[ROOT * N_TAGS + 32 + j] + feats[fbase + 32 + j])
                         : -INFINITY;
    // initial shift = tag-0 alpha0, computed directly by every lane
    float shift = lt[ROOT * N_TAGS + 0] + feats[fbase + 0];

    // ---------------- feats prefetch pipeline ----------------
    float fa[PF], fb[PF];
    #pragma unroll
    for (int d = 0; d < PF; d++) {
        int t = 1 + d;
        fa[d] = feats[fbase + (long)t * N_TAGS + j];
        fb[d] = hasB ? feats[fbase + (long)t * N_TAGS + 32 + j] : 0.0f;
    }

    // ---------------- forward recurrence (warp-local, 1 syncwarp/step) ----
    int p = 0;
    for (int t0 = 1; t0 < len; t0 += PF) {
        #pragma unroll
        for (int d = 0; d < PF; d++) {
            const int t = t0 + d;
            if (t >= len) break;            // uniform across warp

            // next shift = current tag-0 alpha (lagged shift; within ~±35 of
            // true max -> exact fp32 logsumexp)
            float shift_next = __shfl_sync(0xffffffffu, alpha_a, 0);

            float fca = fa[d], fcb = fb[d];
            const int tpre = t + PF;
            if (tpre < MAXT) {
                fa[d] = feats[fbase + (long)tpre * N_TAGS + j];
                if (hasB) fb[d] = feats[fbase + (long)tpre * N_TAGS + 32 + j];
            }

            // publish exp(alpha - shift)
            se[p][j] = __expf(alpha_a - shift);
            if (hasB) se[p][32 + j] = __expf(alpha_b - shift);
            __syncwarp();

            // dot(se, E columns), vectorized smem reads, reused for both cols
            const float4* se4 = (const float4*)se[p];
            float a0 = 0.f, a1 = 0.f, a2 = 0.f, a3 = 0.f;
            float b0 = 0.f, b1 = 0.f, b2 = 0.f, b3 = 0.f;
            #pragma unroll
            for (int i = 0; i < N_TAGS / 4; i++) {
                float4 v = se4[i];
                a0 = fmaf(v.x, Ea[4 * i + 0], a0);
                a1 = fmaf(v.y, Ea[4 * i + 1], a1);
                a2 = fmaf(v.z, Ea[4 * i + 2], a2);
                a3 = fmaf(v.w, Ea[4 * i + 3], a3);
                b0 = fmaf(v.x, Eb[4 * i + 0], b0);
                b1 = fmaf(v.y, Eb[4 * i + 1], b1);
                b2 = fmaf(v.z, Eb[4 * i + 2], b2);
                b3 = fmaf(v.w, Eb[4 * i + 3], b3);
            }
            float sa = (a0 + a1) + (a2 + a3);
            float sb = (b0 + b1) + (b2 + b3);

            // s==0 -> -inf (ROOT column), matches reference semantics
            alpha_a = shift + __logf(sa) + fca;
            alpha_b = shift + __logf(sb) + fcb;   // junk for j>=16, never used
            shift = shift_next;
            p ^= 1;
        }
    }

    // ---------------- partition = lse over 48 terminal scores ----------------
    float pa = alpha_a + lt_end_a;
    float pb = hasB ? (alpha_b + lt_end_b) : -INFINITY;
    float m = fmaxf(pa, pb);
    #pragma unroll
    for (int off = 16; off; off >>= 1)
        m = fmaxf(m, __shfl_xor_sync(0xffffffffu, m, off));

    float ex = __expf(pa - m) + (hasB ? __expf(pb - m) : 0.0f);
    #pragma unroll
    for (int off = 16; off; off >>= 1)
        ex += __shfl_xor_sync(0xffffffffu, ex, off);

    if (j == 0)
        out[b] = m + __logf(ex) - gold;
}

extern "C" void kernel_launch(void* const* d_in, const int* in_sizes, int n_in,
                              void* d_out, int out_size)
{
    const float* feats = nullptr;
    const int*   tags = nullptr;
    const int*   lengths = nullptr;
    const float* lt = nullptr;

    for (int i = 0; i < n_in; i++) {
        switch (in_sizes[i]) {
            case BATCH * MAXT * N_TAGS: feats   = (const float*)d_in[i]; break;
            case BATCH * MAXT:          tags    = (const int*)d_in[i];   break;
            case BATCH:                 lengths = (const int*)d_in[i];   break;
            case N_TAGS * N_TAGS:       lt      = (const float*)d_in[i]; break;
        }
    }

    crf_nll_kernel<<<BATCH, 32>>>(feats, tags, lengths, lt, (float*)d_out);
}

// round 6
// speedup vs baseline: 1.3048x; 1.0290x over previous
#include <cuda_runtime.h>
#include <cuda_bf16.h>
#include <math.h>

#define N_TAGS 48
#define ROOT 46
#define END_TAG 47
#define BATCH 512
#define MAXT 256
#define PF 4            // prefetch depth (per tag column): 8 LDGs in flight

typedef unsigned long long ull;

__device__ __forceinline__ ull fma2(ull a, ull b, ull c) {
    ull d;
    asm("fma.rn.f32x2 %0, %1, %2, %3;" : "=l"(d) : "l"(a), "l"(b), "l"(c));
    return d;
}
__device__ __forceinline__ ull add2(ull a, ull b) {
    ull d;
    asm("add.rn.f32x2 %0, %1, %2;" : "=l"(d) : "l"(a), "l"(b));
    return d;
}
__device__ __forceinline__ ull pack2(float lo, float hi) {
    ull d;
    asm("mov.b64 %0, {%1, %2};" : "=l"(d) : "f"(lo), "f"(hi));
    return d;
}
__device__ __forceinline__ float sum2(ull a) {
    float lo, hi;
    asm("mov.b64 {%0, %1}, %2;" : "=f"(lo), "=f"(hi) : "l"(a));
    return lo + hi;
}

__global__ __launch_bounds__(32)
void crf_nll_kernel(const float* __restrict__ feats,
                    const int* __restrict__ tags,
                    const int* __restrict__ lengths,
                    const float* __restrict__ lt,
                    float* __restrict__ out)
{
    const int b = blockIdx.x;
    const int j = threadIdx.x;              // lane 0..31
    const bool hasB = (j < 16);             // lane also owns tag 32+j

    __shared__ __align__(16) float se[2][N_TAGS];   // r_j = exp(alpha_j - S), double buffered

    const int len = lengths[b];
    const long fbase = (long)b * MAXT * N_TAGS;
    const int tbase = b * MAXT;

    // ---------------- gold score (32 threads, t-strided) ----------------
    float gold;
    {
        float g = 0.0f;
        for (int t = j; t < MAXT; t += 32) {
            if (t < len) {
                int tg = tags[tbase + t];
                g += feats[fbase + t * N_TAGS + tg];
                if (t >= 1) {
                    int tp = tags[tbase + t - 1];
                    g += lt[tp * N_TAGS + tg];
                }
            }
        }
        if (j == 0) {
            int t0 = tags[tbase];
            int tl = tags[tbase + len - 1];
            g += lt[ROOT * N_TAGS + t0] + lt[tl * N_TAGS + END_TAG];
        }
        #pragma unroll
        for (int off = 16; off; off >>= 1)
            g += __shfl_xor_sync(0xffffffffu, g, off);
        gold = g;   // every lane has it
    }

    // ---------------- packed E columns in registers -------------------------
    ull EPa[N_TAGS / 2], EPb[N_TAGS / 2];
    #pragma unroll
    for (int k = 0; k < N_TAGS / 2; k++) {
        float lo = __expf(lt[(2 * k) * N_TAGS + j]);
        float hi = __expf(lt[(2 * k + 1) * N_TAGS + j]);
        EPa[k] = pack2(lo, hi);
        float lob = hasB ? __expf(lt[(2 * k) * N_TAGS + 32 + j]) : 0.0f;
        float hib = hasB ? __expf(lt[(2 * k + 1) * N_TAGS + 32 + j]) : 0.0f;
        EPb[k] = pack2(lob, hib);
    }

    const float lt_end_a = lt[j * N_TAGS + END_TAG];
    const float lt_end_b = hasB ? lt[(32 + j) * N_TAGS + END_TAG] : 0.0f;

    // ---------------- init: S_0 = alpha_0(0); r_j(0) = exp(alpha_j(0)-S) ----
    float S = lt[ROOT * N_TAGS + 0] + feats[fbase + 0];   // same in all lanes
    float r_a = __expf(lt[ROOT * N_TAGS + j] + feats[fbase + j] - S);
    float r_b = hasB ? __expf(lt[ROOT * N_TAGS + 32 + j] + feats[fbase + 32 + j] - S)
                     : 0.0f;

    // ---------------- feats prefetch pipeline ----------------
    float fa[PF], fb[PF];
    #pragma unroll
    for (int d = 0; d < PF; d++) {
        int t = 1 + d;
        fa[d] = feats[fbase + (long)t * N_TAGS + j];
        fb[d] = hasB ? feats[fbase + (long)t * N_TAGS + 32 + j] : 0.0f;
    }

    // publish r(0)
    se[0][j] = r_a;
    if (hasB) se[0][32 + j] = r_b;
    __syncwarp();

    // ---------------- forward recurrence (log-free critical path) ----------
    int cur = 0;
    for (int t0 = 1; t0 < len; t0 += PF) {
        #pragma unroll
        for (int d = 0; d < PF; d++) {
            const int t = t0 + d;
            if (t >= len) break;            // uniform across warp

            float fca = fa[d], fcb = fb[d];
            float f0 = __shfl_sync(0xffffffffu, fca, 0);   // f_0(t)

            const int tpre = t + PF;
            if (tpre < MAXT) {
                fa[d] = feats[fbase + (long)tpre * N_TAGS + j];
                if (hasB) fb[d] = feats[fbase + (long)tpre * N_TAGS + 32 + j];
            }

            // renormalizer from PREVIOUS step's published r_0 — this MUFU
            // chain overlaps the dot below (both start after the last sync)
            float r0prev = se[cur][0];
            float c = __logf(r0prev) + f0;
            float ea = __expf(fca - c);
            float eb = __expf(fcb - c);

            // packed dot: 24 fma.rn.f32x2 per output column
            const ulonglong2* se2 = (const ulonglong2*)se[cur];
            ull a0 = 0, a1 = 0, a2 = 0, a3 = 0;   // bit pattern 0 == (0,0)
            ull b0 = 0, b1 = 0, b2 = 0, b3 = 0;
            #pragma unroll
            for (int i = 0; i < 12; i += 2) {
                ulonglong2 w0 = se2[i];
                ulonglong2 w1 = se2[i + 1];
                a0 = fma2(w0.x, EPa[2 * i + 0], a0);
                a1 = fma2(w0.y, EPa[2 * i + 1], a1);
                a2 = fma2(w1.x, EPa[2 * i + 2], a2);
                a3 = fma2(w1.y, EPa[2 * i + 3], a3);
                b0 = fma2(w0.x, EPb[2 * i + 0], b0);
                b1 = fma2(w0.y, EPb[2 * i + 1], b1);
                b2 = fma2(w1.x, EPb[2 * i + 2], b2);
                b3 = fma2(w1.y, EPb[2 * i + 3], b3);
            }
            float sa = sum2(add2(add2(a0, a1), add2(a2, a3)));
            float sb = sum2(add2(add2(b0, b1), add2(b2, b3)));

            // r'(t): multiplicative update, no log on the critical path
            r_a = sa * ea;
            r_b = sb * eb;                 // junk for j>=16, never stored/used

            se[cur ^ 1][j] = r_a;
            if (hasB) se[cur ^ 1][32 + j] = r_b;
            __syncwarp();

            S += c;                        // scalar shift, identical all lanes
            cur ^= 1;
        }
    }

    // ---------------- partition = lse over 48 terminal scores ----------------
    // alpha_j(T) = S + log(r_j)
    float pa = S + __logf(r_a) + lt_end_a;
    float pb = hasB ? (S + __logf(r_b) + lt_end_b) : -INFINITY;
    float m = fmaxf(pa, pb);
    #pragma unroll
    for (int off = 16; off; off >>= 1)
        m = fmaxf(m, __shfl_xor_sync(0xffffffffu, m, off));

    float ex = __expf(pa - m) + (hasB ? __expf(pb - m) : 0.0f);
    #pragma unroll
    for (int off = 16; off; off >>= 1)
        ex += __shfl_xor_sync(0xffffffffu, ex, off);

    if (j == 0)
        out[b] = m + __logf(ex) - gold;
}

extern "C" void kernel_launch(void* const* d_in, const int* in_sizes, int n_in,
                              void* d_out, int out_size)
{
    const float* feats = nullptr;
    const int*   tags = nullptr;
    const int*   lengths = nullptr;
    const float* lt = nullptr;

    for (int i = 0; i < n_in; i++) {
        switch (in_sizes[i]) {
            case BATCH * MAXT * N_TAGS: feats   = (const float*)d_in[i]; break;
            case BATCH * MAXT:          tags    = (const int*)d_in[i];   break;
            case BATCH:                 lengths = (const int*)d_in[i];   break;
            case N_TAGS * N_TAGS:       lt      = (const float*)d_in[i]; break;
        }
    }

    crf_nll_kernel<<<BATCH, 32>>>(feats, tags, lengths, lt, (float*)d_out);
}